// round 8
// baseline (speedup 1.0000x reference)
#include <cuda_runtime.h>
#include <cuda_bf16.h>
#include <cstdint>
#include <math.h>

#define M_TOK 8192
#define E_DIM 2048
#define F_DIM 8192
#define NW    16777216

// ---------------- device scratch (bf16-exact-integer pipeline) ----------------
__device__ __nv_bfloat16 g_w1b[(size_t)F_DIM * E_DIM];
__device__ __nv_bfloat16 g_w2b[(size_t)F_DIM * E_DIM];
__device__ __nv_bfloat16 g_w3b[(size_t)E_DIM * F_DIM];
__device__ __nv_bfloat16 g_xb [(size_t)M_TOK * E_DIM];
__device__ __nv_bfloat16 g_hb [(size_t)M_TOK * F_DIM];
__device__ float  g_t1 [(size_t)M_TOK * F_DIM];   // x@w1^T (dequantized)
__device__ float  g_t2 [(size_t)M_TOK * F_DIM];   // x@w2^T (dequantized)
__device__ float  g_inv_sx[M_TOK];
__device__ float  g_inv_sh[M_TOK];
__device__ double g_wpart[3 * 256];
__device__ float  g_wdq[3];
__device__ float  g_wsc[3];

// ---------------- prep kernels (proven) ----------------
__global__ void wabs_partial(const float* __restrict__ w, int n, int slot) {
    __shared__ double sd[256];
    int tid = threadIdx.x;
    double acc = 0.0;
    for (int i = blockIdx.x * 256 + tid; i < n; i += 256 * gridDim.x)
        acc += (double)fabsf(w[i]);
    sd[tid] = acc; __syncthreads();
    for (int s = 128; s > 0; s >>= 1) {
        if (tid < s) sd[tid] += sd[tid + s];
        __syncthreads();
    }
    if (tid == 0) g_wpart[slot * 256 + blockIdx.x] = sd[0];
}

__global__ void wscale_final() {
    __shared__ double sd[256];
    int tid = threadIdx.x;
    for (int wsel = 0; wsel < 3; wsel++) {
        sd[tid] = g_wpart[wsel * 256 + tid]; __syncthreads();
        for (int s = 128; s > 0; s >>= 1) {
            if (tid < s) sd[tid] += sd[tid + s];
            __syncthreads();
        }
        if (tid == 0) {
            float mean = (float)(sd[0] / (double)NW);
            float dq = fmaxf(mean, 1e-5f);
            g_wdq[wsel] = dq;
            g_wsc[wsel] = 1.0f / dq;
        }
        __syncthreads();
    }
}

__global__ void quant_w(const float* __restrict__ w, __nv_bfloat16* __restrict__ q,
                        int n, int wi) {
    float s = g_wsc[wi];
    int i = (blockIdx.x * blockDim.x + threadIdx.x) * 4;
    if (i < n) {
        float4 v = *(const float4*)(w + i);
        ushort4 o;
        o.x = __bfloat16_as_ushort(__float2bfloat16_rn(fminf(fmaxf(rintf(v.x * s), -1.0f), 1.0f)));
        o.y = __bfloat16_as_ushort(__float2bfloat16_rn(fminf(fmaxf(rintf(v.y * s), -1.0f), 1.0f)));
        o.z = __bfloat16_as_ushort(__float2bfloat16_rn(fminf(fmaxf(rintf(v.z * s), -1.0f), 1.0f)));
        o.w = __bfloat16_as_ushort(__float2bfloat16_rn(fminf(fmaxf(rintf(v.w * s), -1.0f), 1.0f)));
        *(ushort4*)(q + i) = o;
    }
}

// rmsnorm + absmax int8-grid quant of x (stored bf16)
__global__ void act_quant_x(const float* __restrict__ in, __nv_bfloat16* __restrict__ q,
                            float* __restrict__ inv) {
    const int rowlen = E_DIM;
    int m = blockIdx.x, tid = threadIdx.x;
    const float4* row = (const float4*)(in + (size_t)m * rowlen);
    float4 v[2];
    float ss = 0.0f, mx = 0.0f;
#pragma unroll
    for (int j = 0; j < 2; j++) {
        v[j] = row[tid + j * 256];
        ss += v[j].x * v[j].x + v[j].y * v[j].y + v[j].z * v[j].z + v[j].w * v[j].w;
        mx = fmaxf(mx, fmaxf(fmaxf(fabsf(v[j].x), fabsf(v[j].y)),
                             fmaxf(fabsf(v[j].z), fabsf(v[j].w))));
    }
    __shared__ float sss[256], smx[256];
    sss[tid] = ss; smx[tid] = mx; __syncthreads();
    for (int s = 128; s > 0; s >>= 1) {
        if (tid < s) {
            sss[tid] += sss[tid + s];
            smx[tid] = fmaxf(smx[tid], smx[tid + s]);
        }
        __syncthreads();
    }
    float r = rsqrtf(sss[0] / (float)rowlen + 1e-6f);
    float cmax = fmaxf(smx[0] * r, 1e-5f);
    float scale = 127.0f / cmax;
    if (tid == 0) inv[m] = cmax / 127.0f;

    ushort4* qrow = (ushort4*)(q + (size_t)m * rowlen);
#pragma unroll
    for (int j = 0; j < 2; j++) {
        int qx = __float2int_rn(v[j].x * r * scale);
        int qy = __float2int_rn(v[j].y * r * scale);
        int qz = __float2int_rn(v[j].z * r * scale);
        int qw = __float2int_rn(v[j].w * r * scale);
        qx = min(max(qx, -128), 127); qy = min(max(qy, -128), 127);
        qz = min(max(qz, -128), 127); qw = min(max(qw, -128), 127);
        ushort4 o;
        o.x = __bfloat16_as_ushort(__float2bfloat16_rn((float)qx));
        o.y = __bfloat16_as_ushort(__float2bfloat16_rn((float)qy));
        o.z = __bfloat16_as_ushort(__float2bfloat16_rn((float)qz));
        o.w = __bfloat16_as_ushort(__float2bfloat16_rn((float)qw));
        qrow[tid + j * 256] = o;
    }
}

// SwiGLU(t1,t2) -> h, then rmsnorm + absmax int8-grid quant (stored bf16)
__global__ void act_quant_swiglu(const float* __restrict__ t1, const float* __restrict__ t2,
                                 __nv_bfloat16* __restrict__ q, float* __restrict__ inv) {
    const int rowlen = F_DIM;
    int m = blockIdx.x, tid = threadIdx.x;
    const float4* r1 = (const float4*)(t1 + (size_t)m * rowlen);
    const float4* r2 = (const float4*)(t2 + (size_t)m * rowlen);
    float4 v[8];
    float ss = 0.0f, mx = 0.0f;
#pragma unroll
    for (int j = 0; j < 8; j++) {
        float4 a = r1[tid + j * 256];
        float4 b = r2[tid + j * 256];
        float4 h;
        h.x = a.x / (1.0f + expf(-a.x)) * b.x;
        h.y = a.y / (1.0f + expf(-a.y)) * b.y;
        h.z = a.z / (1.0f + expf(-a.z)) * b.z;
        h.w = a.w / (1.0f + expf(-a.w)) * b.w;
        v[j] = h;
        ss += h.x * h.x + h.y * h.y + h.z * h.z + h.w * h.w;
        mx = fmaxf(mx, fmaxf(fmaxf(fabsf(h.x), fabsf(h.y)),
                             fmaxf(fabsf(h.z), fabsf(h.w))));
    }
    __shared__ float sss[256], smx[256];
    sss[tid] = ss; smx[tid] = mx; __syncthreads();
    for (int s = 128; s > 0; s >>= 1) {
        if (tid < s) {
            sss[tid] += sss[tid + s];
            smx[tid] = fmaxf(smx[tid], smx[tid + s]);
        }
        __syncthreads();
    }
    float r = rsqrtf(sss[0] / (float)rowlen + 1e-6f);
    float cmax = fmaxf(smx[0] * r, 1e-5f);
    float scale = 127.0f / cmax;
    if (tid == 0) inv[m] = cmax / 127.0f;

    ushort4* qrow = (ushort4*)(q + (size_t)m * rowlen);
#pragma unroll
    for (int j = 0; j < 8; j++) {
        int qx = __float2int_rn(v[j].x * r * scale);
        int qy = __float2int_rn(v[j].y * r * scale);
        int qz = __float2int_rn(v[j].z * r * scale);
        int qw = __float2int_rn(v[j].w * r * scale);
        qx = min(max(qx, -128), 127); qy = min(max(qy, -128), 127);
        qz = min(max(qz, -128), 127); qw = min(max(qw, -128), 127);
        ushort4 o;
        o.x = __bfloat16_as_ushort(__float2bfloat16_rn((float)qx));
        o.y = __bfloat16_as_ushort(__float2bfloat16_rn((float)qy));
        o.z = __bfloat16_as_ushort(__float2bfloat16_rn((float)qz));
        o.w = __bfloat16_as_ushort(__float2bfloat16_rn((float)qw));
        qrow[tid + j * 256] = o;
    }
}

// ---------------- bf16 GEMM: 256x128 CTA tile, 512 threads (16 warps) ----------------
#define BM 256
#define BN 128
#define SROW 144          // 128B data + 16B pad; 16B-aligned rows (cp.async/ldmatrix)
#define ATILE (256 * SROW)
#define BTILE (128 * SROW)
#define STAGEB (ATILE + BTILE)
#define NSTG 3

__device__ __forceinline__ uint32_t smem_u32(const void* p) {
    uint32_t a;
    asm("{ .reg .u64 t; cvta.to.shared.u64 t, %1; cvt.u32.u64 %0, t; }" : "=r"(a) : "l"(p));
    return a;
}
__device__ __forceinline__ void cp16(uint32_t sdst, const void* gsrc) {
    asm volatile("cp.async.cg.shared.global [%0], [%1], 16;\n" :: "r"(sdst), "l"(gsrc) : "memory");
}
__device__ __forceinline__ void cp_commit() { asm volatile("cp.async.commit_group;\n" ::: "memory"); }
__device__ __forceinline__ void cp_wait0()  { asm volatile("cp.async.wait_group 0;\n" ::: "memory"); }
__device__ __forceinline__ void cp_wait1()  { asm volatile("cp.async.wait_group 1;\n" ::: "memory"); }
__device__ __forceinline__ void ldsm4(uint32_t* r, uint32_t addr) {
    asm volatile("ldmatrix.sync.aligned.m8n8.x4.shared.b16 {%0,%1,%2,%3}, [%4];"
        : "=r"(r[0]), "=r"(r[1]), "=r"(r[2]), "=r"(r[3]) : "r"(addr));
}
__device__ __forceinline__ void mma_bf16(float* c, const uint32_t* a, const uint32_t* b) {
    asm volatile(
        "mma.sync.aligned.m16n8k16.row.col.f32.bf16.bf16.f32 "
        "{%0,%1,%2,%3},{%4,%5,%6,%7},{%8,%9},{%0,%1,%2,%3};\n"
        : "+f"(c[0]), "+f"(c[1]), "+f"(c[2]), "+f"(c[3])
        : "r"(a[0]), "r"(a[1]), "r"(a[2]), "r"(a[3]), "r"(b[0]), "r"(b[1]));
}

__global__ void __launch_bounds__(512, 1) gemm_bf(
    const __nv_bfloat16* __restrict__ A,
    const __nv_bfloat16* __restrict__ B,
    int K, const float* __restrict__ invA, int wi,
    float* __restrict__ out, int ldo)
{
    extern __shared__ char smem[];
    const uint32_t sb = smem_u32(smem);
    int tid = threadIdx.x;
    int m0 = blockIdx.y * BM, n0 = blockIdx.x * BN;
    size_t Kb = (size_t)K * 2;
    const char* Ab = (const char*)A + (size_t)m0 * Kb;
    const char* Bb = (const char*)B + (size_t)n0 * Kb;
    int KT = K / 64;     // 64 K-elems (128 bytes) per stage

    // cp.async: A = 2048 16B-chunks, B = 1024 chunks; 512 threads
    auto issue = [&](int kt) {
        uint32_t base = sb + (kt % NSTG) * STAGEB;
        size_t k0b = (size_t)kt * 128;
#pragma unroll
        for (int it = 0; it < 4; it++) {           // A: 4 * 512 = 2048 chunks
            int c = it * 512 + tid;
            int row = c >> 3, col = (c & 7) * 16;
            cp16(base + (uint32_t)(row * SROW + col), Ab + (size_t)row * Kb + k0b + col);
        }
#pragma unroll
        for (int it = 0; it < 2; it++) {           // B: 2 * 512 = 1024 chunks
            int c = it * 512 + tid;
            int row = c >> 3, col = (c & 7) * 16;
            cp16(base + ATILE + (uint32_t)(row * SROW + col), Bb + (size_t)row * Kb + k0b + col);
        }
        cp_commit();
    };

    int wid = tid >> 5, lane = tid & 31;
    int wm = wid >> 2, wn = wid & 3;     // 4 (M) x 4 (N) warps; warp tile 64x32
    int g = lane >> 2, t4 = lane & 3;

    uint32_t offA[4];
#pragma unroll
    for (int im = 0; im < 4; im++)
        offA[im] = (uint32_t)((wm * 64 + im * 16 + (lane & 15)) * SROW + (lane >> 4) * 16);
    uint32_t offB[2];
#pragma unroll
    for (int ib = 0; ib < 2; ib++)
        offB[ib] = (uint32_t)((wn * 32 + ib * 16 + (lane & 7) + ((lane >> 4) & 1) * 8) * SROW
                              + ((lane >> 3) & 1) * 16);

    float acc[4][4][4] = {};

    issue(0);
    issue(1);
    for (int kt = 0; kt < KT; kt++) {
        if (kt == KT - 1) cp_wait0(); else cp_wait1();
        __syncthreads();
        if (kt + 2 < KT) issue(kt + 2);

        const uint32_t base = sb + (kt % NSTG) * STAGEB;
        const uint32_t Asm = base, Bsm = base + ATILE;

#pragma unroll
        for (int ks = 0; ks < 4; ks++) {           // 16 K-elems per step
            const uint32_t kb = ks * 32;
            uint32_t a[4][4];
#pragma unroll
            for (int im = 0; im < 4; im++) ldsm4(a[im], Asm + offA[im] + kb);
            uint32_t b[2][4];
#pragma unroll
            for (int ib = 0; ib < 2; ib++) ldsm4(b[ib], Bsm + offB[ib] + kb);
#pragma unroll
            for (int ib = 0; ib < 2; ib++)
#pragma unroll
                for (int sub = 0; sub < 2; sub++)
#pragma unroll
                    for (int im = 0; im < 4; im++)
                        mma_bf16(acc[im][ib * 2 + sub], a[im], &b[ib][sub * 2]);
        }
        __syncthreads();
    }

    // epilogue: dequant only (accumulators are exact integers)
    float dq = g_wdq[wi];
#pragma unroll
    for (int im = 0; im < 4; im++) {
#pragma unroll
        for (int h2 = 0; h2 < 2; h2++) {
            int row = m0 + wm * 64 + im * 16 + g + h2 * 8;
            float ia = invA[row] * dq;
#pragma unroll
            for (int in = 0; in < 4; in++) {
                int col = n0 + wn * 32 + in * 8 + t4 * 2;
                size_t o = (size_t)row * ldo + col;
                out[o]     = acc[im][in][h2 * 2 + 0] * ia;
                out[o + 1] = acc[im][in][h2 * 2 + 1] * ia;
            }
        }
    }
}

// ---------------- launch ----------------
extern "C" void kernel_launch(void* const* d_in, const int* in_sizes, int n_in,
                              void* d_out, int out_size) {
    const float* x  = (const float*)d_in[0];
    const float* w1 = (const float*)d_in[1];
    const float* w2 = (const float*)d_in[2];
    const float* w3 = (const float*)d_in[3];
    float* out = (float*)d_out;

    void *p_w1b, *p_w2b, *p_w3b, *p_xb, *p_hb, *p_t1, *p_t2, *p_isx, *p_ish;
    cudaGetSymbolAddress(&p_w1b, g_w1b);
    cudaGetSymbolAddress(&p_w2b, g_w2b);
    cudaGetSymbolAddress(&p_w3b, g_w3b);
    cudaGetSymbolAddress(&p_xb,  g_xb);
    cudaGetSymbolAddress(&p_hb,  g_hb);
    cudaGetSymbolAddress(&p_t1,  g_t1);
    cudaGetSymbolAddress(&p_t2,  g_t2);
    cudaGetSymbolAddress(&p_isx, g_inv_sx);
    cudaGetSymbolAddress(&p_ish, g_inv_sh);

    const int SMB = NSTG * STAGEB;    // 3 * 55296 = 165888 B
    cudaFuncSetAttribute(gemm_bf, cudaFuncAttributeMaxDynamicSharedMemorySize, SMB);

    // 1) weight scales
    wabs_partial<<<256, 256>>>(w1, NW, 0);
    wabs_partial<<<256, 256>>>(w2, NW, 1);
    wabs_partial<<<256, 256>>>(w3, NW, 2);
    wscale_final<<<1, 256>>>();

    // 2) ternary weight quantization (bf16 {-1,0,1})
    quant_w<<<NW / 1024, 256>>>(w1, (__nv_bfloat16*)p_w1b, NW, 0);
    quant_w<<<NW / 1024, 256>>>(w2, (__nv_bfloat16*)p_w2b, NW, 1);
    quant_w<<<NW / 1024, 256>>>(w3, (__nv_bfloat16*)p_w3b, NW, 2);

    // 3) rmsnorm + int8-grid quant of x
    act_quant_x<<<M_TOK, 256>>>(x, (__nv_bfloat16*)p_xb, (float*)p_isx);

    // 4) GEMM1a: x@w1^T -> t1 ; GEMM1b: x@w2^T -> t2
    dim3 g1(F_DIM / BN, M_TOK / BM);     // (64, 32)
    gemm_bf<<<g1, 512, SMB>>>((const __nv_bfloat16*)p_xb, (const __nv_bfloat16*)p_w1b,
                              E_DIM, (const float*)p_isx, 0, (float*)p_t1, F_DIM);
    gemm_bf<<<g1, 512, SMB>>>((const __nv_bfloat16*)p_xb, (const __nv_bfloat16*)p_w2b,
                              E_DIM, (const float*)p_isx, 1, (float*)p_t2, F_DIM);

    // 5) SwiGLU + rmsnorm + quant of h
    act_quant_swiglu<<<M_TOK, 256>>>((const float*)p_t1, (const float*)p_t2,
                                     (__nv_bfloat16*)p_hb, (float*)p_ish);

    // 6) GEMM2: h@w3^T -> out
    dim3 g2(E_DIM / BN, M_TOK / BM);     // (16, 32)
    gemm_bf<<<g2, 512, SMB>>>((const __nv_bfloat16*)p_hb, (const __nv_bfloat16*)p_w3b,
                              F_DIM, (const float*)p_ish, 2, out, E_DIM);
}